// round 11
// baseline (speedup 1.0000x reference)
#include <cuda_runtime.h>
#include <cstdint>

// ---------------- problem constants ----------------
#define INPUT_SIZE 10000
#define STEP       250
#define OUT_PER_G  50
#define GROUPS     39
#define BATCH      4096
#define OUT_COLS   (GROUPS * OUT_PER_G)   // 1950

// ---------------- tiling ----------------
#define KPAD    512            // K padded to 16 chunks of 32 (covers 500 + shift 2)
#define KC      32             // floats per K chunk (128 B rows in smem)
#define NCHUNK  16
#define TM      128
#define TNS     56             // computed N cols (50 real + 6 pad)
#define STAGES  3
#define A_BYTES (TM * KC * 4)               // 16384
#define B_BYTES (TNS * KC * 4)              // 7168
#define STAGE_BYTES (A_BYTES + B_BYTES)     // 23552
#define SMEM_BYTES  (STAGES * STAGE_BYTES)  // 70656 -> 3 CTAs/SM

// Padded + tf32-rounded + (odd-g) shifted W: [39][50][512] fp32 (~4 MB)
__device__ float g_Wpad[GROUPS * OUT_PER_G * KPAD];

// ---------------- helpers ----------------
__device__ __forceinline__ uint32_t smem_u32(const void* p) {
    uint32_t a;
    asm("{ .reg .u64 t; cvta.to.shared.u64 t, %1; cvt.u32.u64 %0, t; }" : "=r"(a) : "l"(p));
    return a;
}
__device__ __forceinline__ void cp16z(uint32_t dst, const void* src, uint32_t sz) {
    asm volatile("cp.async.cg.shared.global [%0], [%1], 16, %2;"
                 :: "r"(dst), "l"(src), "r"(sz));
}
__device__ __forceinline__ void cp16(uint32_t dst, const void* src) {
    asm volatile("cp.async.cg.shared.global [%0], [%1], 16;" :: "r"(dst), "l"(src));
}
__device__ __forceinline__ void ldm4(uint32_t& r0, uint32_t& r1, uint32_t& r2, uint32_t& r3,
                                     uint32_t addr) {
    asm volatile("ldmatrix.sync.aligned.m8n8.x4.shared.b16 {%0,%1,%2,%3}, [%4];"
                 : "=r"(r0), "=r"(r1), "=r"(r2), "=r"(r3) : "r"(addr));
}
__device__ __forceinline__ void ldm2(uint32_t& r0, uint32_t& r1, uint32_t addr) {
    asm volatile("ldmatrix.sync.aligned.m8n8.x2.shared.b16 {%0,%1}, [%2];"
                 : "=r"(r0), "=r"(r1) : "r"(addr));
}
__device__ __forceinline__ void mma8(float* c, const uint32_t* a, uint32_t b0, uint32_t b1) {
    asm volatile(
        "mma.sync.aligned.m16n8k8.row.col.f32.tf32.tf32.f32 "
        "{%0,%1,%2,%3},{%4,%5,%6,%7},{%8,%9},{%0,%1,%2,%3};"
        : "+f"(c[0]), "+f"(c[1]), "+f"(c[2]), "+f"(c[3])
        : "r"(a[0]), "r"(a[1]), "r"(a[2]), "r"(a[3]), "r"(b0), "r"(b1));
}
__device__ __forceinline__ uint32_t tf32_rna(uint32_t bits) {
    float f = __uint_as_float(bits);
    uint32_t r;
    asm("cvt.rna.tf32.f32 %0, %1;" : "=r"(r) : "f"(f));
    return r;
}

// -------- W repack: [39,50,500] -> [39,50,512], tf32-rounded, shifted +2 for odd g --------
// out[b,g,o] = sum_{k'} x[b, g*250 - 2*(g&1) + k'] * Wpad[g,o,k']   (16B-aligned x window)
__global__ void prep_w_kernel(const float* __restrict__ W) {
    int i = blockIdx.x * blockDim.x + threadIdx.x;
    if (i >= GROUPS * OUT_PER_G * KPAD) return;
    int k   = i & (KPAD - 1);
    int row = i >> 9;                        // group*50 + o
    int grp = row / OUT_PER_G;
    int ks  = k - 2 * (grp & 1);             // source k after shift
    float v = (ks >= 0 && ks < 500) ? W[row * 500 + ks] : 0.0f;
    uint32_t u;
    asm("cvt.rna.tf32.f32 %0, %1;" : "=r"(u) : "f"(v));
    g_Wpad[i] = __uint_as_float(u);
}

// ------- main kernel: 128 threads, 4 warps x (32 x 56) warp-private tiles -------
__global__ void __launch_bounds__(128, 3)
peak_kernel(const float* __restrict__ x, float* __restrict__ out) {
    extern __shared__ char smem[];
    const uint32_t sb = smem_u32(smem);

    const int tid  = threadIdx.x;
    const int lane = tid & 31;
    const int wid  = tid >> 5;      // 4 warps along M, 32 rows each; all 56 cols

    const int g  = blockIdx.x % GROUPS;     // g fastest -> overlapping x stays L2-hot
    const int mt = blockIdx.x / GROUPS;
    const int gcol = g * STEP - 2 * (g & 1);   // 16B-aligned window start

    // A-load mapping: 1024 cp16 per chunk, 8 per thread (row = i>>3, f4 = i&7)
    const int arow0 = tid >> 3;     // rows arow0 + 16t
    const int af4   = tid & 7;

    // ldmatrix fragment address components (tf32 m16n8k8 layout)
    const int rA  = (lane & 7) + ((lane >> 3) & 1) * 8;  // A row within 16-row tile
    const int c4A = lane >> 4;                           // A f4-col (0/1)
    const int rB  = (lane & 7) + (lane >> 4) * 8;        // B row within 16-row pair
    const int c4B = (lane >> 3) & 1;                     // B f4-col (0/1)
    const int swA = rA & 7, swB = rB & 7;
    // x2 ldmatrix addressing for B rows 48..55 (lanes 0..15 supply addresses)
    const int l16  = lane & 15;
    const int rB2  = 48 + (l16 & 7);
    const int c4B2 = l16 >> 3;
    const int swB2 = l16 & 7;

    uint32_t rowoffA[2], rowoffB[3], rowoffB2;
#pragma unroll
    for (int i = 0; i < 2; i++)
        rowoffA[i] = (uint32_t)(wid * 32 + i * 16 + rA) * 128;
#pragma unroll
    for (int i = 0; i < 3; i++)
        rowoffB[i] = (uint32_t)(i * 16 + rB) * 128 + A_BYTES;
    rowoffB2 = (uint32_t)rB2 * 128 + A_BYTES;

    float acc[2][7][4];
#pragma unroll
    for (int i = 0; i < 2; i++)
#pragma unroll
        for (int j = 0; j < 7; j++)
#pragma unroll
            for (int k = 0; k < 4; k++) acc[i][j][k] = 0.0f;

    const float* xbase = x + (size_t)mt * TM * INPUT_SIZE;

    auto loadA = [&](int c, int s) {
        const uint32_t ab = sb + s * STAGE_BYTES;
        const int colc = gcol + c * KC;
        const float* src0 = xbase + colc + af4 * 4;
        if (colc + KC <= INPUT_SIZE) {          // fast path: no bounds checks
#pragma unroll
            for (int t = 0; t < 8; t++) {
                const int row = arow0 + t * 16;
                uint32_t bo = (uint32_t)row * 128 + (uint32_t)af4 * 16;
                uint32_t sw = bo ^ ((bo >> 3) & 0x70);
                cp16(ab + sw, src0 + (size_t)row * INPUT_SIZE);
            }
        } else {                                 // g=38 tail chunk only
#pragma unroll
            for (int t = 0; t < 8; t++) {
                const int row = arow0 + t * 16;
                const int col = colc + af4 * 4;
                uint32_t bo = (uint32_t)row * 128 + (uint32_t)af4 * 16;
                uint32_t sw = bo ^ ((bo >> 3) & 0x70);
                uint32_t sz = (col < INPUT_SIZE) ? 16u : 0u;
                cp16z(ab + sw, sz ? (const void*)(src0 + (size_t)row * INPUT_SIZE)
                                  : (const void*)x, sz);
            }
        }
    };
    auto loadB = [&](int c, int s) {
        const uint32_t bb = sb + s * STAGE_BYTES + A_BYTES;
        const float* wb = g_Wpad + (size_t)g * OUT_PER_G * KPAD + c * KC;
#pragma unroll
        for (int t = 0; t < 4; t++) {
            const int i = tid + t * 128;
            if (i < OUT_PER_G * 8) {         // 400 cp16 (rows 50..55 garbage, cols unused)
                const int n = i >> 3, f4 = i & 7;
                uint32_t bo = (uint32_t)n * 128 + (uint32_t)f4 * 16;
                uint32_t sw = bo ^ ((bo >> 3) & 0x70);
                cp16(bb + sw, wb + (size_t)n * KPAD + f4 * 4);
            }
        }
    };

    // compute with register double-buffered fragments: ldmatrix of slice ks+1
    // issues BEFORE the mma chain of slice ks -> LDSM latency hidden in-warp.
    auto compute = [&](int s) {
        const uint32_t stage = sb + s * STAGE_BYTES;
        uint32_t a[2][2][4], b[2][3][4], b3[2][2];

        auto ldfrag = [&](int ks, int buf) {
#pragma unroll
            for (int m = 0; m < 2; m++) {
                uint32_t addr = stage + rowoffA[m] + ((uint32_t)((ks * 2 + c4A) ^ swA) << 4);
                ldm4(a[buf][m][0], a[buf][m][1], a[buf][m][2], a[buf][m][3], addr);
            }
#pragma unroll
            for (int np = 0; np < 3; np++) {
                uint32_t addr = stage + rowoffB[np] + ((uint32_t)((ks * 2 + c4B) ^ swB) << 4);
                ldm4(b[buf][np][0], b[buf][np][1], b[buf][np][2], b[buf][np][3], addr);
            }
            uint32_t addr = stage + rowoffB2 + ((uint32_t)((ks * 2 + c4B2) ^ swB2) << 4);
            ldm2(b3[buf][0], b3[buf][1], addr);
        };

        ldfrag(0, 0);
#pragma unroll
        for (int ks = 0; ks < 4; ks++) {
            const int cur = ks & 1;
            if (ks < 3) ldfrag(ks + 1, cur ^ 1);   // prefetch next slice
            // round A to tf32 nearest (W pre-rounded) -> no truncation bias
#pragma unroll
            for (int m = 0; m < 2; m++)
#pragma unroll
                for (int j = 0; j < 4; j++) a[cur][m][j] = tf32_rna(a[cur][m][j]);
#pragma unroll
            for (int m = 0; m < 2; m++) {
#pragma unroll
                for (int nt = 0; nt < 6; nt++)
                    mma8(acc[m][nt], a[cur][m],
                         b[cur][nt >> 1][(nt & 1) * 2], b[cur][nt >> 1][(nt & 1) * 2 + 1]);
                mma8(acc[m][6], a[cur][m], b3[cur][0], b3[cur][1]);
            }
        }
    };

    // ---- prologue: fill 2 stages ----
#pragma unroll
    for (int c = 0; c < STAGES - 1; c++) {
        loadA(c, c);
        loadB(c, c);
        asm volatile("cp.async.commit_group;" ::: "memory");
    }

    // ---- main pipeline: 2-chunk lookahead, one barrier per chunk ----
    int s = 0, sn = STAGES - 1;
    for (int c = 0; c < NCHUNK; c++) {
        asm volatile("cp.async.wait_group 1;" ::: "memory");
        __syncthreads();     // chunk c resident; all warps done computing c-1
        if (c + STAGES - 1 < NCHUNK) {
            loadA(c + STAGES - 1, sn);
            loadB(c + STAGES - 1, sn);
        }
        asm volatile("cp.async.commit_group;" ::: "memory");  // uniform group accounting
        compute(s);
        s  = (s  == STAGES - 1) ? 0 : s + 1;
        sn = (sn == STAGES - 1) ? 0 : sn + 1;
    }

    // ---- epilogue: relu + store (only real cols < 50) ----
    const int gout = g * OUT_PER_G;
#pragma unroll
    for (int m = 0; m < 2; m++) {
        const int r0 = mt * TM + wid * 32 + m * 16 + (lane >> 2);
#pragma unroll
        for (int nt = 0; nt < 7; nt++) {
            const int cl = nt * 8 + 2 * (lane & 3);
            if (cl < OUT_PER_G) {
                float2 v;
                v.x = fmaxf(acc[m][nt][0], 0.0f);
                v.y = fmaxf(acc[m][nt][1], 0.0f);
                *(float2*)(out + (size_t)r0 * OUT_COLS + gout + cl) = v;
                v.x = fmaxf(acc[m][nt][2], 0.0f);
                v.y = fmaxf(acc[m][nt][3], 0.0f);
                *(float2*)(out + (size_t)(r0 + 8) * OUT_COLS + gout + cl) = v;
            }
        }
    }
}

// ---------------- launch ----------------
extern "C" void kernel_launch(void* const* d_in, const int* in_sizes, int n_in,
                              void* d_out, int out_size) {
    const float* x = (const float*)d_in[0];
    const float* W = (const float*)d_in[1];
    float* out = (float*)d_out;

    {
        const int total = GROUPS * OUT_PER_G * KPAD;
        prep_w_kernel<<<(total + 255) / 256, 256>>>(W);
    }

    cudaFuncSetAttribute(peak_kernel,
                         cudaFuncAttributeMaxDynamicSharedMemorySize, SMEM_BYTES);
    dim3 grid(GROUPS * (BATCH / TM));    // 1248 CTAs, g fastest
    peak_kernel<<<grid, 128, SMEM_BYTES>>>(x, out);
}

// round 12
// speedup vs baseline: 1.0481x; 1.0481x over previous
#include <cuda_runtime.h>
#include <cstdint>

// ---------------- problem constants ----------------
#define INPUT_SIZE 10000
#define STEP       250
#define OUT_PER_G  50
#define GROUPS     39
#define BATCH      4096
#define OUT_COLS   (GROUPS * OUT_PER_G)   // 1950

// ---------------- tiling ----------------
#define KPAD    512            // K padded to 16 chunks of 32 (covers 500 + shift 2)
#define KC      32             // floats per K chunk (128 B rows in smem)
#define NCHUNK  16
#define TM      128
#define TNS     56             // computed N cols (50 real + 6 pad)
#define STAGES  3
#define A_BYTES (TM * KC * 4)               // 16384
#define B_BYTES (TNS * KC * 4)              // 7168
#define STAGE_BYTES (A_BYTES + B_BYTES)     // 23552
#define SMEM_BYTES  (STAGES * STAGE_BYTES)  // 70656 -> 3 CTAs/SM

// Padded + tf32-rounded + (odd-g) shifted W: [39][50][512] fp32 (~4 MB)
__device__ float g_Wpad[GROUPS * OUT_PER_G * KPAD];

// ---------------- helpers ----------------
__device__ __forceinline__ uint32_t smem_u32(const void* p) {
    uint32_t a;
    asm("{ .reg .u64 t; cvta.to.shared.u64 t, %1; cvt.u32.u64 %0, t; }" : "=r"(a) : "l"(p));
    return a;
}
__device__ __forceinline__ void cp16z(uint32_t dst, const void* src, uint32_t sz) {
    asm volatile("cp.async.cg.shared.global [%0], [%1], 16, %2;"
                 :: "r"(dst), "l"(src), "r"(sz));
}
__device__ __forceinline__ void cp16(uint32_t dst, const void* src) {
    asm volatile("cp.async.cg.shared.global [%0], [%1], 16;" :: "r"(dst), "l"(src));
}
__device__ __forceinline__ void ldm4(uint32_t& r0, uint32_t& r1, uint32_t& r2, uint32_t& r3,
                                     uint32_t addr) {
    asm volatile("ldmatrix.sync.aligned.m8n8.x4.shared.b16 {%0,%1,%2,%3}, [%4];"
                 : "=r"(r0), "=r"(r1), "=r"(r2), "=r"(r3) : "r"(addr));
}
__device__ __forceinline__ void ldm2(uint32_t& r0, uint32_t& r1, uint32_t addr) {
    asm volatile("ldmatrix.sync.aligned.m8n8.x2.shared.b16 {%0,%1}, [%2];"
                 : "=r"(r0), "=r"(r1) : "r"(addr));
}
__device__ __forceinline__ void mma8(float* c, const uint32_t* a, uint32_t b0, uint32_t b1) {
    asm volatile(
        "mma.sync.aligned.m16n8k8.row.col.f32.tf32.tf32.f32 "
        "{%0,%1,%2,%3},{%4,%5,%6,%7},{%8,%9},{%0,%1,%2,%3};"
        : "+f"(c[0]), "+f"(c[1]), "+f"(c[2]), "+f"(c[3])
        : "r"(a[0]), "r"(a[1]), "r"(a[2]), "r"(a[3]), "r"(b0), "r"(b1));
}

// -------- W repack: [39,50,500] -> [39,50,512], tf32-rounded, shifted +2 for odd g --------
// out[b,g,o] = sum_{k'} x[b, g*250 - 2*(g&1) + k'] * Wpad[g,o,k']   (16B-aligned x window)
__global__ void prep_w_kernel(const float* __restrict__ W) {
    int i = blockIdx.x * blockDim.x + threadIdx.x;
    if (i >= GROUPS * OUT_PER_G * KPAD) return;
    int k   = i & (KPAD - 1);
    int row = i >> 9;                        // group*50 + o
    int grp = row / OUT_PER_G;
    int ks  = k - 2 * (grp & 1);             // source k after shift
    float v = (ks >= 0 && ks < 500) ? W[row * 500 + ks] : 0.0f;
    uint32_t u;
    asm("cvt.rna.tf32.f32 %0, %1;" : "=r"(u) : "f"(v));
    g_Wpad[i] = __uint_as_float(u);
}

// ------- main kernel: 128 threads, 4 warps x (32 x 56) warp-private tiles -------
// x operand is fed RAW fp32 to the tf32 mma (HW truncation). W is pre-rounded rna;
// truncation bias on x ~= 1.8e-4 relative on the positive-sum output — well under 1e-3.
__global__ void __launch_bounds__(128, 3)
peak_kernel(const float* __restrict__ x, float* __restrict__ out) {
    extern __shared__ char smem[];
    const uint32_t sb = smem_u32(smem);

    const int tid  = threadIdx.x;
    const int lane = tid & 31;
    const int wid  = tid >> 5;      // 4 warps along M, 32 rows each; all 56 cols

    const int g  = blockIdx.x % GROUPS;     // g fastest -> overlapping x stays L2-hot
    const int mt = blockIdx.x / GROUPS;
    const int gcol = g * STEP - 2 * (g & 1);   // 16B-aligned window start

    // A-load mapping: 1024 cp16 per chunk, 8 per thread (row = i>>3, f4 = i&7)
    const int arow0 = tid >> 3;     // rows arow0 + 16t
    const int af4   = tid & 7;

    // ldmatrix fragment address components (tf32 m16n8k8 layout)
    const int rA  = (lane & 7) + ((lane >> 3) & 1) * 8;  // A row within 16-row tile
    const int c4A = lane >> 4;                           // A f4-col (0/1)
    const int rB  = (lane & 7) + (lane >> 4) * 8;        // B row within 16-row pair
    const int c4B = (lane >> 3) & 1;                     // B f4-col (0/1)
    const int swA = rA & 7, swB = rB & 7;
    // x2 ldmatrix addressing for B rows 48..55 (lanes 0..15 supply addresses)
    const int l16  = lane & 15;
    const int rB2  = 48 + (l16 & 7);
    const int c4B2 = l16 >> 3;
    const int swB2 = l16 & 7;

    uint32_t rowoffA[2], rowoffB[3], rowoffB2;
#pragma unroll
    for (int i = 0; i < 2; i++)
        rowoffA[i] = (uint32_t)(wid * 32 + i * 16 + rA) * 128;
#pragma unroll
    for (int i = 0; i < 3; i++)
        rowoffB[i] = (uint32_t)(i * 16 + rB) * 128 + A_BYTES;
    rowoffB2 = (uint32_t)rB2 * 128 + A_BYTES;

    float acc[2][7][4];
#pragma unroll
    for (int i = 0; i < 2; i++)
#pragma unroll
        for (int j = 0; j < 7; j++)
#pragma unroll
            for (int k = 0; k < 4; k++) acc[i][j][k] = 0.0f;

    const float* xbase = x + (size_t)mt * TM * INPUT_SIZE;

    auto loadA = [&](int c, int s) {
        const uint32_t ab = sb + s * STAGE_BYTES;
        const int colc = gcol + c * KC;
        const float* src0 = xbase + colc + af4 * 4;
        if (colc + KC <= INPUT_SIZE) {          // fast path: no bounds checks
#pragma unroll
            for (int t = 0; t < 8; t++) {
                const int row = arow0 + t * 16;
                uint32_t bo = (uint32_t)row * 128 + (uint32_t)af4 * 16;
                uint32_t sw = bo ^ ((bo >> 3) & 0x70);
                cp16(ab + sw, src0 + (size_t)row * INPUT_SIZE);
            }
        } else {                                 // g=38 tail chunk only
#pragma unroll
            for (int t = 0; t < 8; t++) {
                const int row = arow0 + t * 16;
                const int col = colc + af4 * 4;
                uint32_t bo = (uint32_t)row * 128 + (uint32_t)af4 * 16;
                uint32_t sw = bo ^ ((bo >> 3) & 0x70);
                uint32_t sz = (col < INPUT_SIZE) ? 16u : 0u;
                cp16z(ab + sw, sz ? (const void*)(src0 + (size_t)row * INPUT_SIZE)
                                  : (const void*)x, sz);
            }
        }
    };
    auto loadB = [&](int c, int s) {
        const uint32_t bb = sb + s * STAGE_BYTES + A_BYTES;
        const float* wb = g_Wpad + (size_t)g * OUT_PER_G * KPAD + c * KC;
        // 400 cp16: 3 full rounds of 128 + 16-lane tail (no per-round predicate)
#pragma unroll
        for (int t = 0; t < 3; t++) {
            const int i = tid + t * 128;
            const int n = i >> 3, f4 = i & 7;
            uint32_t bo = (uint32_t)n * 128 + (uint32_t)f4 * 16;
            uint32_t sw = bo ^ ((bo >> 3) & 0x70);
            cp16(bb + sw, wb + (size_t)n * KPAD + f4 * 4);
        }
        if (tid < 16) {
            const int i = tid + 384;
            const int n = i >> 3, f4 = i & 7;
            uint32_t bo = (uint32_t)n * 128 + (uint32_t)f4 * 16;
            uint32_t sw = bo ^ ((bo >> 3) & 0x70);
            cp16(bb + sw, wb + (size_t)n * KPAD + f4 * 4);
        }
    };

    auto compute = [&](int s) {
        const uint32_t stage = sb + s * STAGE_BYTES;
#pragma unroll
        for (int ks = 0; ks < 4; ks++) {
            uint32_t a[2][4], b[3][4], b3[2];
#pragma unroll
            for (int m = 0; m < 2; m++) {
                uint32_t addr = stage + rowoffA[m] + ((uint32_t)((ks * 2 + c4A) ^ swA) << 4);
                ldm4(a[m][0], a[m][1], a[m][2], a[m][3], addr);
            }
#pragma unroll
            for (int np = 0; np < 3; np++) {
                uint32_t addr = stage + rowoffB[np] + ((uint32_t)((ks * 2 + c4B) ^ swB) << 4);
                ldm4(b[np][0], b[np][1], b[np][2], b[np][3], addr);
            }
            {   // B rows 48..55, k lo/hi tiles
                uint32_t addr = stage + rowoffB2 + ((uint32_t)((ks * 2 + c4B2) ^ swB2) << 4);
                ldm2(b3[0], b3[1], addr);
            }
            // mma directly on raw fp32 fragments (HW tf32 truncation of x)
#pragma unroll
            for (int m = 0; m < 2; m++) {
#pragma unroll
                for (int nt = 0; nt < 6; nt++)
                    mma8(acc[m][nt], a[m], b[nt >> 1][(nt & 1) * 2], b[nt >> 1][(nt & 1) * 2 + 1]);
                mma8(acc[m][6], a[m], b3[0], b3[1]);
            }
        }
    };

    // ---- prologue: fill 2 stages ----
#pragma unroll
    for (int c = 0; c < STAGES - 1; c++) {
        loadA(c, c);
        loadB(c, c);
        asm volatile("cp.async.commit_group;" ::: "memory");
    }

    // ---- main pipeline: 2-chunk lookahead, one barrier per chunk ----
    int s = 0, sn = STAGES - 1;
    for (int c = 0; c < NCHUNK; c++) {
        asm volatile("cp.async.wait_group 1;" ::: "memory");
        __syncthreads();     // chunk c resident; all warps done computing c-1
        if (c + STAGES - 1 < NCHUNK) {
            loadA(c + STAGES - 1, sn);
            loadB(c + STAGES - 1, sn);
        }
        asm volatile("cp.async.commit_group;" ::: "memory");  // uniform group accounting
        compute(s);
        s  = (s  == STAGES - 1) ? 0 : s + 1;
        sn = (sn == STAGES - 1) ? 0 : sn + 1;
    }

    // ---- epilogue: relu + store (only real cols < 50) ----
    const int gout = g * OUT_PER_G;
#pragma unroll
    for (int m = 0; m < 2; m++) {
        const int r0 = mt * TM + wid * 32 + m * 16 + (lane >> 2);
#pragma unroll
        for (int nt = 0; nt < 7; nt++) {
            const int cl = nt * 8 + 2 * (lane & 3);
            if (cl < OUT_PER_G) {
                float2 v;
                v.x = fmaxf(acc[m][nt][0], 0.0f);
                v.y = fmaxf(acc[m][nt][1], 0.0f);
                *(float2*)(out + (size_t)r0 * OUT_COLS + gout + cl) = v;
                v.x = fmaxf(acc[m][nt][2], 0.0f);
                v.y = fmaxf(acc[m][nt][3], 0.0f);
                *(float2*)(out + (size_t)(r0 + 8) * OUT_COLS + gout + cl) = v;
            }
        }
    }
}

// ---------------- launch ----------------
extern "C" void kernel_launch(void* const* d_in, const int* in_sizes, int n_in,
                              void* d_out, int out_size) {
    const float* x = (const float*)d_in[0];
    const float* W = (const float*)d_in[1];
    float* out = (float*)d_out;

    {
        const int total = GROUPS * OUT_PER_G * KPAD;
        prep_w_kernel<<<(total + 255) / 256, 256>>>(W);
    }

    cudaFuncSetAttribute(peak_kernel,
                         cudaFuncAttributeMaxDynamicSharedMemorySize, SMEM_BYTES);
    dim3 grid(GROUPS * (BATCH / TM));    // 1248 CTAs, g fastest
    peak_kernel<<<grid, 128, SMEM_BYTES>>>(x, out);
}

// round 13
// speedup vs baseline: 1.1621x; 1.1087x over previous
#include <cuda_runtime.h>
#include <cuda.h>
#include <cstdint>

// ---------------- problem constants ----------------
#define INPUT_SIZE 10000
#define STEP       250
#define OUT_PER_G  50
#define GROUPS     39
#define BATCH      4096
#define OUT_COLS   (GROUPS * OUT_PER_G)   // 1950

// ---------------- tiling ----------------
#define KPAD    512            // K padded to 16 chunks of 32 (covers 500 + shift 2)
#define KC      32             // floats per K chunk (= 128 B rows, SW128 atom)
#define NCHUNK  16
#define TM      128
#define STAGES  3
#define A_BYTES     (TM * 128)                  // 16384
#define B_SMEM_ROWS 56                          // rows 50..55 stale, cols unused
#define B_TMA_BYTES (OUT_PER_G * 128)           // 6400 (TMA writes 50 rows)
#define STAGE_BYTES (A_BYTES + B_SMEM_ROWS * 128)   // 23552
#define SMEM_BYTES  (1024 + STAGES * STAGE_BYTES)   // 71680 -> 3 CTAs/SM
#define TX_BYTES    (A_BYTES + B_TMA_BYTES)     // 22784 per chunk

// Padded + tf32-rounded + (odd-g) shifted W: [39*50][512] fp32 (~4 MB)
__device__ float g_Wpad[GROUPS * OUT_PER_G * KPAD];

// ---------------- helpers ----------------
__device__ __forceinline__ uint32_t smem_u32(const void* p) {
    uint32_t a;
    asm("{ .reg .u64 t; cvta.to.shared.u64 t, %1; cvt.u32.u64 %0, t; }" : "=r"(a) : "l"(p));
    return a;
}
__device__ __forceinline__ void mbar_init(uint32_t mbar, uint32_t cnt) {
    asm volatile("mbarrier.init.shared.b64 [%0], %1;" :: "r"(mbar), "r"(cnt) : "memory");
}
__device__ __forceinline__ void mbar_expect_tx(uint32_t mbar, uint32_t tx) {
    asm volatile("mbarrier.arrive.expect_tx.shared.b64 _, [%0], %1;"
                 :: "r"(mbar), "r"(tx) : "memory");
}
__device__ __forceinline__ void mbar_wait(uint32_t mbar, uint32_t parity) {
    asm volatile(
        "{\n\t.reg .pred P;\n\t"
        "LAB_%=:\n\t"
        "mbarrier.try_wait.parity.shared.b64 P, [%0], %1;\n\t"
        "@!P bra LAB_%=;\n\t}"
        :: "r"(mbar), "r"(parity) : "memory");
}
__device__ __forceinline__ void tma2d(uint32_t dst, const CUtensorMap* m,
                                      int cx, int cy, uint32_t mbar) {
    asm volatile(
        "cp.async.bulk.tensor.2d.shared::cta.global.tile.mbarrier::complete_tx::bytes "
        "[%0], [%1, {%2, %3}], [%4];"
        :: "r"(dst), "l"(m), "r"(cx), "r"(cy), "r"(mbar) : "memory");
}
__device__ __forceinline__ void ldm4(uint32_t& r0, uint32_t& r1, uint32_t& r2, uint32_t& r3,
                                     uint32_t addr) {
    asm volatile("ldmatrix.sync.aligned.m8n8.x4.shared.b16 {%0,%1,%2,%3}, [%4];"
                 : "=r"(r0), "=r"(r1), "=r"(r2), "=r"(r3) : "r"(addr));
}
__device__ __forceinline__ void ldm2(uint32_t& r0, uint32_t& r1, uint32_t addr) {
    asm volatile("ldmatrix.sync.aligned.m8n8.x2.shared.b16 {%0,%1}, [%2];"
                 : "=r"(r0), "=r"(r1) : "r"(addr));
}
__device__ __forceinline__ void mma8(float* c, const uint32_t* a, uint32_t b0, uint32_t b1) {
    asm volatile(
        "mma.sync.aligned.m16n8k8.row.col.f32.tf32.tf32.f32 "
        "{%0,%1,%2,%3},{%4,%5,%6,%7},{%8,%9},{%0,%1,%2,%3};"
        : "+f"(c[0]), "+f"(c[1]), "+f"(c[2]), "+f"(c[3])
        : "r"(a[0]), "r"(a[1]), "r"(a[2]), "r"(a[3]), "r"(b0), "r"(b1));
}

// -------- W repack: [39,50,500] -> [39,50,512], tf32-rounded, shifted +2 for odd g --------
// out[b,g,o] = sum_{k'} x[b, g*250 - 2*(g&1) + k'] * Wpad[g,o,k']
__global__ void prep_w_kernel(const float* __restrict__ W) {
    int i = blockIdx.x * blockDim.x + threadIdx.x;
    if (i >= GROUPS * OUT_PER_G * KPAD) return;
    int k   = i & (KPAD - 1);
    int row = i >> 9;                        // group*50 + o
    int grp = row / OUT_PER_G;
    int ks  = k - 2 * (grp & 1);             // source k after shift
    float v = (ks >= 0 && ks < 500) ? W[row * 500 + ks] : 0.0f;
    uint32_t u;
    asm("cvt.rna.tf32.f32 %0, %1;" : "=r"(u) : "f"(v));
    g_Wpad[i] = __uint_as_float(u);
}

// ------- main kernel: 128 threads, 4 warps x (32 x 56) warp-private tiles -------
// All loads via TMA (2 ops/chunk, elected thread). x fed raw fp32 to tf32 mma
// (HW truncation; W pre-rounded rna) -> bias ~1.8e-4, under 1e-3.
__global__ void __launch_bounds__(128, 3)
peak_kernel(const __grid_constant__ CUtensorMap tmA,
            const __grid_constant__ CUtensorMap tmB,
            float* __restrict__ out) {
    extern __shared__ char smem[];
    const uint32_t sb0   = smem_u32(smem);
    const uint32_t mbar0 = sb0;                                // 3 x 8B mbarriers
    const uint32_t tiles = (sb0 + 64 + 1023) & ~1023u;         // 1024-aligned tile base

    const int tid  = threadIdx.x;
    const int lane = tid & 31;
    const int wid  = tid >> 5;      // 4 warps along M, 32 rows each; all 56 cols

    const int g  = blockIdx.x % GROUPS;     // g fastest -> overlapping x stays L2-hot
    const int mt = blockIdx.x / GROUPS;
    const int gcol = g * STEP - 2 * (g & 1);   // 16B-aligned window start

    // ldmatrix fragment address components (tf32 m16n8k8 layout)
    const int rA  = (lane & 7) + ((lane >> 3) & 1) * 8;  // A row within 16-row tile
    const int c4A = lane >> 4;                           // A f4-col (0/1)
    const int rB  = (lane & 7) + (lane >> 4) * 8;        // B row within 16-row pair
    const int c4B = (lane >> 3) & 1;                     // B f4-col (0/1)
    const int swA = rA & 7, swB = rB & 7;
    // x2 ldmatrix addressing for B rows 48..55 (lanes 0..15 supply addresses)
    const int l16  = lane & 15;
    const int rB2  = 48 + (l16 & 7);
    const int c4B2 = l16 >> 3;
    const int swB2 = l16 & 7;

    uint32_t rowoffA[2], rowoffB[3], rowoffB2;
#pragma unroll
    for (int i = 0; i < 2; i++)
        rowoffA[i] = (uint32_t)(wid * 32 + i * 16 + rA) * 128;
#pragma unroll
    for (int i = 0; i < 3; i++)
        rowoffB[i] = (uint32_t)(i * 16 + rB) * 128 + A_BYTES;
    rowoffB2 = (uint32_t)rB2 * 128 + A_BYTES;

    float acc[2][7][4];
#pragma unroll
    for (int i = 0; i < 2; i++)
#pragma unroll
        for (int j = 0; j < 7; j++)
#pragma unroll
            for (int k = 0; k < 4; k++) acc[i][j][k] = 0.0f;

    // ---- mbarrier init ----
    if (tid == 0) {
#pragma unroll
        for (int s = 0; s < STAGES; s++) mbar_init(mbar0 + 8 * s, 1);
    }
    __syncthreads();

    auto issue = [&](int c, int s) {
        const uint32_t mb = mbar0 + 8 * s;
        const uint32_t ad = tiles + s * STAGE_BYTES;
        mbar_expect_tx(mb, TX_BYTES);
        tma2d(ad,           &tmA, gcol + c * KC, mt * TM,        mb);  // A: 128x32f, OOB=0
        tma2d(ad + A_BYTES, &tmB, c * KC,        g * OUT_PER_G,  mb);  // B: 50x32f
    };

    // ---- prologue: issue chunks 0,1 ----
    if (tid == 0) { issue(0, 0); issue(1, 1); }

    auto compute = [&](int s) {
        const uint32_t stage = tiles + s * STAGE_BYTES;
#pragma unroll
        for (int ks = 0; ks < 4; ks++) {
            uint32_t a[2][4], b[3][4], b3[2];
#pragma unroll
            for (int m = 0; m < 2; m++) {
                uint32_t addr = stage + rowoffA[m] + ((uint32_t)((ks * 2 + c4A) ^ swA) << 4);
                ldm4(a[m][0], a[m][1], a[m][2], a[m][3], addr);
            }
#pragma unroll
            for (int np = 0; np < 3; np++) {
                uint32_t addr = stage + rowoffB[np] + ((uint32_t)((ks * 2 + c4B) ^ swB) << 4);
                ldm4(b[np][0], b[np][1], b[np][2], b[np][3], addr);
            }
            {   // B rows 48..55 (50..55 stale -> cols discarded)
                uint32_t addr = stage + rowoffB2 + ((uint32_t)((ks * 2 + c4B2) ^ swB2) << 4);
                ldm2(b3[0], b3[1], addr);
            }
#pragma unroll
            for (int m = 0; m < 2; m++) {
#pragma unroll
                for (int nt = 0; nt < 6; nt++)
                    mma8(acc[m][nt], a[m], b[nt >> 1][(nt & 1) * 2], b[nt >> 1][(nt & 1) * 2 + 1]);
                mma8(acc[m][6], a[m], b3[0], b3[1]);
            }
        }
    };

    // ---- main pipeline: 3 stages, 2-chunk lookahead, one barrier per chunk ----
    for (int c = 0; c < NCHUNK; c++) {
        const int s = c % STAGES;
        mbar_wait(mbar0 + 8 * s, (c / STAGES) & 1);   // TMA for chunk c complete
        __syncthreads();                               // all warps done with compute(c-1)
        if (tid == 0 && c + 2 < NCHUNK) issue(c + 2, (c + 2) % STAGES);
        compute(s);
    }

    // ---- epilogue: relu + store (only real cols < 50) ----
    const int gout = g * OUT_PER_G;
#pragma unroll
    for (int m = 0; m < 2; m++) {
        const int r0 = mt * TM + wid * 32 + m * 16 + (lane >> 2);
#pragma unroll
        for (int nt = 0; nt < 7; nt++) {
            const int cl = nt * 8 + 2 * (lane & 3);
            if (cl < OUT_PER_G) {
                float2 v;
                v.x = fmaxf(acc[m][nt][0], 0.0f);
                v.y = fmaxf(acc[m][nt][1], 0.0f);
                *(float2*)(out + (size_t)r0 * OUT_COLS + gout + cl) = v;
                v.x = fmaxf(acc[m][nt][2], 0.0f);
                v.y = fmaxf(acc[m][nt][3], 0.0f);
                *(float2*)(out + (size_t)(r0 + 8) * OUT_COLS + gout + cl) = v;
            }
        }
    }
}

// ---------------- launch ----------------
typedef CUresult (*EncFn)(CUtensorMap*, CUtensorMapDataType, cuuint32_t, void*,
                          const cuuint64_t*, const cuuint64_t*, const cuuint32_t*,
                          const cuuint32_t*, CUtensorMapInterleave, CUtensorMapSwizzle,
                          CUtensorMapL2promotion, CUtensorMapFloatOOBfill);

extern "C" void kernel_launch(void* const* d_in, const int* in_sizes, int n_in,
                              void* d_out, int out_size) {
    const float* x = (const float*)d_in[0];
    const float* W = (const float*)d_in[1];
    float* out = (float*)d_out;

    // 1) repack W into zero-padded, tf32-rounded, shifted buffer
    {
        const int total = GROUPS * OUT_PER_G * KPAD;
        prep_w_kernel<<<(total + 255) / 256, 256>>>(W);
    }

    // 2) tensor maps (host-side; no device alloc, graph-capture safe)
    void* pfn = nullptr;
    cudaDriverEntryPointQueryResult qres;
    cudaGetDriverEntryPointByVersion("cuTensorMapEncodeTiled", &pfn, 12000,
                                     cudaEnableDefault, &qres);
    EncFn enc = (EncFn)pfn;

    void* wptr = nullptr;
    cudaGetSymbolAddress(&wptr, g_Wpad);

    CUtensorMap tmA, tmB;
    {
        cuuint64_t dims[2]    = {INPUT_SIZE, BATCH};
        cuuint64_t strides[1] = {INPUT_SIZE * sizeof(float)};
        cuuint32_t box[2]     = {KC, TM};
        cuuint32_t es[2]      = {1, 1};
        enc(&tmA, CU_TENSOR_MAP_DATA_TYPE_FLOAT32, 2, (void*)x, dims, strides, box, es,
            CU_TENSOR_MAP_INTERLEAVE_NONE, CU_TENSOR_MAP_SWIZZLE_128B,
            CU_TENSOR_MAP_L2_PROMOTION_L2_128B, CU_TENSOR_MAP_FLOAT_OOB_FILL_NONE);
    }
    {
        cuuint64_t dims[2]    = {KPAD, GROUPS * OUT_PER_G};
        cuuint64_t strides[1] = {KPAD * sizeof(float)};
        cuuint32_t box[2]     = {KC, OUT_PER_G};
        cuuint32_t es[2]      = {1, 1};
        enc(&tmB, CU_TENSOR_MAP_DATA_TYPE_FLOAT32, 2, wptr, dims, strides, box, es,
            CU_TENSOR_MAP_INTERLEAVE_NONE, CU_TENSOR_MAP_SWIZZLE_128B,
            CU_TENSOR_MAP_L2_PROMOTION_L2_128B, CU_TENSOR_MAP_FLOAT_OOB_FILL_NONE);
    }

    // 3) main fused group-GEMM + relu
    cudaFuncSetAttribute(peak_kernel,
                         cudaFuncAttributeMaxDynamicSharedMemorySize, SMEM_BYTES);
    dim3 grid(GROUPS * (BATCH / TM));    // 1248 CTAs, g fastest
    peak_kernel<<<grid, 128, SMEM_BYTES>>>(tmA, tmB, out);
}